// round 5
// baseline (speedup 1.0000x reference)
#include <cuda_runtime.h>
#include <math.h>

#define D_MODEL 1024
#define NHEAD 16
#define HEAD_DIM 64
#define B_ 2
#define T_ 2048
#define M_TOT (B_ * T_)   // 4096

// Scratch (allocation-free: __device__ globals)
__device__ float g_Q[M_TOT * D_MODEL];
__device__ float g_K[M_TOT * D_MODEL];
__device__ float g_V[M_TOT * D_MODEL];
__device__ float g_O[M_TOT * D_MODEL];

// ---------------------------------------------------------------------------
// SGEMM: C[M,N] = A[M,K] @ W[K,N] + bias[N]
// BM=BN=128, BK=8, 256 threads, 8x8 micro-tile
// ---------------------------------------------------------------------------
__global__ __launch_bounds__(256) void sgemm_bias_kernel(
    const float* __restrict__ A, const float* __restrict__ W,
    const float* __restrict__ bias, float* __restrict__ C,
    int M, int N, int K)
{
    const int BM = 128, BN = 128, BK = 8;
    __shared__ float As[BK][BM];   // transposed: As[k][m]
    __shared__ float Ws[BK][BN];   // natural:    Ws[k][n]

    int tid = threadIdx.x;
    int tx = tid % 16, ty = tid / 16;
    int bm = blockIdx.y * BM;
    int bn = blockIdx.x * BN;

    float acc[8][8];
#pragma unroll
    for (int i = 0; i < 8; i++)
#pragma unroll
        for (int j = 0; j < 8; j++) acc[i][j] = 0.f;

    int a_row = tid >> 1;            // 0..127
    int a_col = (tid & 1) * 4;       // 0 or 4
    int w_row = tid >> 5;            // 0..7
    int w_col = (tid & 31) * 4;      // 0..124

    for (int k0 = 0; k0 < K; k0 += BK) {
        float4 av = *(const float4*)&A[(size_t)(bm + a_row) * K + k0 + a_col];
        As[a_col + 0][a_row] = av.x;
        As[a_col + 1][a_row] = av.y;
        As[a_col + 2][a_row] = av.z;
        As[a_col + 3][a_row] = av.w;
        float4 wv = *(const float4*)&W[(size_t)(k0 + w_row) * N + bn + w_col];
        *(float4*)&Ws[w_row][w_col] = wv;
        __syncthreads();

#pragma unroll
        for (int k = 0; k < BK; k++) {
            float a[8], b[8];
            *(float4*)&a[0] = *(const float4*)&As[k][ty * 8];
            *(float4*)&a[4] = *(const float4*)&As[k][ty * 8 + 4];
            *(float4*)&b[0] = *(const float4*)&Ws[k][tx * 8];
            *(float4*)&b[4] = *(const float4*)&Ws[k][tx * 8 + 4];
#pragma unroll
            for (int i = 0; i < 8; i++)
#pragma unroll
                for (int j = 0; j < 8; j++)
                    acc[i][j] += a[i] * b[j];
        }
        __syncthreads();
    }

#pragma unroll
    for (int i = 0; i < 8; i++) {
        int m = bm + ty * 8 + i;
#pragma unroll
        for (int j = 0; j < 8; j += 4) {
            int n = bn + tx * 8 + j;
            float4 o;
            o.x = acc[i][j + 0] + bias[n + 0];
            o.y = acc[i][j + 1] + bias[n + 1];
            o.z = acc[i][j + 2] + bias[n + 2];
            o.w = acc[i][j + 3] + bias[n + 3];
            *(float4*)&C[(size_t)m * N + n] = o;
        }
    }
}

// ---------------------------------------------------------------------------
// RoPE in-place on Q and K; Q also gets the 1/sqrt(hd) score scale folded in.
// One thread per (b,t,h,i) pair, i in [0,32).
// ---------------------------------------------------------------------------
__global__ void rope_kernel(float* __restrict__ Q, float* __restrict__ K)
{
    int idx = blockIdx.x * blockDim.x + threadIdx.x;
    const int TOTAL = B_ * T_ * NHEAD * 32;
    if (idx >= TOTAL) return;
    int i = idx & 31;
    int h = (idx >> 5) & (NHEAD - 1);
    int t = (idx >> 9) & (T_ - 1);
    int b = idx >> 20;

    float freq = (float)t / powf(10000.0f, (float)i / 32.0f);
    float s, c;
    sincosf(freq, &s, &c);

    int base = ((b * T_ + t) * D_MODEL) + h * HEAD_DIM;
    const float scale = 0.125f;  // 64^-0.5

    float ql = Q[base + i], qr = Q[base + i + 32];
    Q[base + i]      = (ql * c - qr * s) * scale;
    Q[base + i + 32] = (ql * s + qr * c) * scale;

    float kl = K[base + i], kr = K[base + i + 32];
    K[base + i]      = kl * c - kr * s;
    K[base + i + 32] = kl * s + kr * c;
}

// ---------------------------------------------------------------------------
// Flash attention: 64-query tile per block, loop over 64-key tiles.
// grid = (T/64, NHEAD, B), 256 threads (16x16), 4x4 micro-tiles.
// smem: Qst[64][64] d-major, Kst[64][64] d-major, Vs[64][64] k-major,
//       Ps[64][65] q-major, fq[64], fk[64]
// ---------------------------------------------------------------------------
#define ATT_SMEM_FLOATS (64*64*3 + 64*65 + 128)
#define ATT_SMEM_BYTES (ATT_SMEM_FLOATS * 4)

__global__ __launch_bounds__(256) void attn_kernel(
    const float* __restrict__ Q, const float* __restrict__ K,
    const float* __restrict__ V, float* __restrict__ O,
    const float* __restrict__ frac,
    const float* __restrict__ alpha_pos, const float* __restrict__ alpha_neg)
{
    extern __shared__ float sm[];
    float* Qst = sm;                  // [64][64] (d, q)
    float* Kst = Qst + 64 * 64;       // [64][64] (d, k)
    float* Vs  = Kst + 64 * 64;       // [64][64] (k, dv)
    float* Ps  = Vs + 64 * 64;        // [64][65] (q, k) padded
    float* fq  = Ps + 64 * 65;
    float* fk  = fq + 64;

    int tid = threadIdx.x;
    int tx = tid % 16, ty = tid / 16;
    int qt = blockIdx.x;
    int h  = blockIdx.y;
    int b  = blockIdx.z;
    int t0 = qt * 64;

    const float ap = alpha_pos[h];
    const float an = alpha_neg[h];

    // Load Q tile (transpose to d-major)
    int lk = tid & 63;       // element row within tile
    int lc = tid >> 6;       // 0..3
#pragma unroll
    for (int it = 0; it < 4; it++) {
        int c = lc + it * 4;  // chunk 0..15 -> dims c*4 .. c*4+3
        const float* gp = &Q[((size_t)(b * T_ + t0 + lk)) * D_MODEL + h * HEAD_DIM + c * 4];
        float4 v = *(const float4*)gp;
        Qst[(c * 4 + 0) * 64 + lk] = v.x;
        Qst[(c * 4 + 1) * 64 + lk] = v.y;
        Qst[(c * 4 + 2) * 64 + lk] = v.z;
        Qst[(c * 4 + 3) * 64 + lk] = v.w;
    }
    if (tid < 64) fq[tid] = frac[b * T_ + t0 + tid];

    float m_i[4], l_i[4], o_acc[4][4];
#pragma unroll
    for (int i = 0; i < 4; i++) {
        m_i[i] = -INFINITY;
        l_i[i] = 0.f;
#pragma unroll
        for (int j = 0; j < 4; j++) o_acc[i][j] = 0.f;
    }
    __syncthreads();

    float fqr[4];
#pragma unroll
    for (int i = 0; i < 4; i++) fqr[i] = fq[ty * 4 + i];

    for (int kt = 0; kt < T_ / 64; kt++) {
        int tk0 = kt * 64;
        // Load K tile (transpose) + V tile (natural) + fk
#pragma unroll
        for (int it = 0; it < 4; it++) {
            int c = lc + it * 4;
            const float* gk = &K[((size_t)(b * T_ + tk0 + lk)) * D_MODEL + h * HEAD_DIM + c * 4];
            float4 kv = *(const float4*)gk;
            Kst[(c * 4 + 0) * 64 + lk] = kv.x;
            Kst[(c * 4 + 1) * 64 + lk] = kv.y;
            Kst[(c * 4 + 2) * 64 + lk] = kv.z;
            Kst[(c * 4 + 3) * 64 + lk] = kv.w;
            const float* gv = &V[((size_t)(b * T_ + tk0 + lk)) * D_MODEL + h * HEAD_DIM + c * 4];
            *(float4*)&Vs[lk * 64 + c * 4] = *(const float4*)gv;
        }
        if (tid < 64) fk[tid] = frac[b * T_ + tk0 + tid];
        __syncthreads();

        // S = Q K^T (Q pre-scaled)
        float s[4][4];
#pragma unroll
        for (int i = 0; i < 4; i++)
#pragma unroll
            for (int j = 0; j < 4; j++) s[i][j] = 0.f;

#pragma unroll 8
        for (int d = 0; d < 64; d++) {
            float4 a4 = *(const float4*)&Qst[d * 64 + ty * 4];
            float4 b4 = *(const float4*)&Kst[d * 64 + tx * 4];
            float a[4] = {a4.x, a4.y, a4.z, a4.w};
            float bb[4] = {b4.x, b4.y, b4.z, b4.w};
#pragma unroll
            for (int i = 0; i < 4; i++)
#pragma unroll
                for (int j = 0; j < 4; j++)
                    s[i][j] += a[i] * bb[j];
        }

        // frac bias
        float fkc[4];
#pragma unroll
        for (int j = 0; j < 4; j++) fkc[j] = fk[tx * 4 + j];
#pragma unroll
        for (int i = 0; i < 4; i++)
#pragma unroll
            for (int j = 0; j < 4; j++) {
                float d = fkc[j] - fqr[i];
                s[i][j] += (d > 0.f) ? ap * d : an * d;
            }

        // online softmax update (rows reduced across the 16 tx lanes)
#pragma unroll
        for (int i = 0; i < 4; i++) {
            float m = fmaxf(fmaxf(s[i][0], s[i][1]), fmaxf(s[i][2], s[i][3]));
            m = fmaxf(m, __shfl_xor_sync(0xffffffffu, m, 1));
            m = fmaxf(m, __shfl_xor_sync(0xffffffffu, m, 2));
            m = fmaxf(m, __shfl_xor_sync(0xffffffffu, m, 4));
            m = fmaxf(m, __shfl_xor_sync(0xffffffffu, m, 8));
            float m_new = fmaxf(m_i[i], m);
            float corr = expf(m_i[i] - m_new);
            float p0 = expf(s[i][0] - m_new);
            float p1 = expf(s[i][1] - m_new);
            float p2 = expf(s[i][2] - m_new);
            float p3 = expf(s[i][3] - m_new);
            float r = p0 + p1 + p2 + p3;
            r += __shfl_xor_sync(0xffffffffu, r, 1);
            r += __shfl_xor_sync(0xffffffffu, r, 2);
            r += __shfl_xor_sync(0xffffffffu, r, 4);
            r += __shfl_xor_sync(0xffffffffu, r, 8);
            l_i[i] = l_i[i] * corr + r;
            m_i[i] = m_new;
#pragma unroll
            for (int j = 0; j < 4; j++) o_acc[i][j] *= corr;
            // store P (q-major, padded rows)
            Ps[(ty * 4 + i) * 65 + tx * 4 + 0] = p0;
            Ps[(ty * 4 + i) * 65 + tx * 4 + 1] = p1;
            Ps[(ty * 4 + i) * 65 + tx * 4 + 2] = p2;
            Ps[(ty * 4 + i) * 65 + tx * 4 + 3] = p3;
        }
        __syncthreads();

        // O += P @ V
#pragma unroll 8
        for (int k = 0; k < 64; k++) {
            float a[4];
#pragma unroll
            for (int i = 0; i < 4; i++) a[i] = Ps[(ty * 4 + i) * 65 + k];
            float4 b4 = *(const float4*)&Vs[k * 64 + tx * 4];
            float bb[4] = {b4.x, b4.y, b4.z, b4.w};
#pragma unroll
            for (int i = 0; i < 4; i++)
#pragma unroll
                for (int j = 0; j < 4; j++)
                    o_acc[i][j] += a[i] * bb[j];
        }
        __syncthreads();
    }

    // epilogue: normalize and write to g_O in [B,T,D] layout
#pragma unroll
    for (int i = 0; i < 4; i++) {
        float inv = 1.0f / l_i[i];
        int t = t0 + ty * 4 + i;
        float4 o;
        o.x = o_acc[i][0] * inv;
        o.y = o_acc[i][1] * inv;
        o.z = o_acc[i][2] * inv;
        o.w = o_acc[i][3] * inv;
        *(float4*)&O[((size_t)(b * T_ + t)) * D_MODEL + h * HEAD_DIM + tx * 4] = o;
    }
}

// ---------------------------------------------------------------------------
// Launch
// Inputs: 0 query, 1 key, 2 value, 3 frac, 4 Wq, 5 Wk, 6 Wv, 7 Wo,
//         8 bq, 9 bk, 10 bv, 11 bo, 12 alpha_pos, 13 alpha_neg
// ---------------------------------------------------------------------------
extern "C" void kernel_launch(void* const* d_in, const int* in_sizes, int n_in,
                              void* d_out, int out_size)
{
    const float* query = (const float*)d_in[0];
    const float* key   = (const float*)d_in[1];
    const float* value = (const float*)d_in[2];
    const float* frac  = (const float*)d_in[3];
    const float* Wq    = (const float*)d_in[4];
    const float* Wk    = (const float*)d_in[5];
    const float* Wv    = (const float*)d_in[6];
    const float* Wo    = (const float*)d_in[7];
    const float* bq    = (const float*)d_in[8];
    const float* bk    = (const float*)d_in[9];
    const float* bv    = (const float*)d_in[10];
    const float* bo    = (const float*)d_in[11];
    const float* a_pos = (const float*)d_in[12];
    const float* a_neg = (const float*)d_in[13];
    float* out = (float*)d_out;

    float *pQ, *pK, *pV, *pO;
    cudaGetSymbolAddress((void**)&pQ, g_Q);
    cudaGetSymbolAddress((void**)&pK, g_K);
    cudaGetSymbolAddress((void**)&pV, g_V);
    cudaGetSymbolAddress((void**)&pO, g_O);

    dim3 gemm_grid(D_MODEL / 128, M_TOT / 128);

    sgemm_bias_kernel<<<gemm_grid, 256>>>(query, Wq, bq, pQ, M_TOT, D_MODEL, D_MODEL);
    sgemm_bias_kernel<<<gemm_grid, 256>>>(key,   Wk, bk, pK, M_TOT, D_MODEL, D_MODEL);
    sgemm_bias_kernel<<<gemm_grid, 256>>>(value, Wv, bv, pV, M_TOT, D_MODEL, D_MODEL);

    int rope_threads = B_ * T_ * NHEAD * 32;
    rope_kernel<<<(rope_threads + 255) / 256, 256>>>(pQ, pK);

    cudaFuncSetAttribute(attn_kernel, cudaFuncAttributeMaxDynamicSharedMemorySize, ATT_SMEM_BYTES);
    attn_kernel<<<dim3(T_ / 64, NHEAD, B_), 256, ATT_SMEM_BYTES>>>(
        pQ, pK, pV, pO, frac, a_pos, a_neg);

    sgemm_bias_kernel<<<gemm_grid, 256>>>(pO, Wo, bo, out, M_TOT, D_MODEL, D_MODEL);
}

// round 6
// speedup vs baseline: 1.0539x; 1.0539x over previous
#include <cuda_runtime.h>
#include <math.h>

#define D_MODEL 1024
#define NHEAD 16
#define HEAD_DIM 64
#define B_ 2
#define T_ 2048
#define M_TOT (B_ * T_)   // 4096

// Scratch (allocation-free: __device__ globals)
__device__ float g_Q[M_TOT * D_MODEL];
__device__ float g_K[M_TOT * D_MODEL];
__device__ float g_V[M_TOT * D_MODEL];
__device__ float g_O[M_TOT * D_MODEL];

// ---------------------------------------------------------------------------
// SGEMM: C[M,N] = A[M,K] @ W[K,N] + bias[N]
// BM=BN=128, BK=8, 256 threads, 8x8 micro-tile
// ---------------------------------------------------------------------------
__global__ __launch_bounds__(256) void sgemm_bias_kernel(
    const float* __restrict__ A, const float* __restrict__ W,
    const float* __restrict__ bias, float* __restrict__ C,
    int M, int N, int K)
{
    const int BM = 128, BN = 128, BK = 8;
    __shared__ float As[BK][BM];   // transposed: As[k][m]
    __shared__ float Ws[BK][BN];   // natural:    Ws[k][n]

    int tid = threadIdx.x;
    int tx = tid % 16, ty = tid / 16;
    int bm = blockIdx.y * BM;
    int bn = blockIdx.x * BN;

    float acc[8][8];
#pragma unroll
    for (int i = 0; i < 8; i++)
#pragma unroll
        for (int j = 0; j < 8; j++) acc[i][j] = 0.f;

    int a_row = tid >> 1;            // 0..127
    int a_col = (tid & 1) * 4;       // 0 or 4
    int w_row = tid >> 5;            // 0..7
    int w_col = (tid & 31) * 4;      // 0..124

    for (int k0 = 0; k0 < K; k0 += BK) {
        float4 av = *(const float4*)&A[(size_t)(bm + a_row) * K + k0 + a_col];
        As[a_col + 0][a_row] = av.x;
        As[a_col + 1][a_row] = av.y;
        As[a_col + 2][a_row] = av.z;
        As[a_col + 3][a_row] = av.w;
        float4 wv = *(const float4*)&W[(size_t)(k0 + w_row) * N + bn + w_col];
        *(float4*)&Ws[w_row][w_col] = wv;
        __syncthreads();

#pragma unroll
        for (int k = 0; k < BK; k++) {
            float a[8], b[8];
            *(float4*)&a[0] = *(const float4*)&As[k][ty * 8];
            *(float4*)&a[4] = *(const float4*)&As[k][ty * 8 + 4];
            *(float4*)&b[0] = *(const float4*)&Ws[k][tx * 8];
            *(float4*)&b[4] = *(const float4*)&Ws[k][tx * 8 + 4];
#pragma unroll
            for (int i = 0; i < 8; i++)
#pragma unroll
                for (int j = 0; j < 8; j++)
                    acc[i][j] += a[i] * b[j];
        }
        __syncthreads();
    }

#pragma unroll
    for (int i = 0; i < 8; i++) {
        int m = bm + ty * 8 + i;
#pragma unroll
        for (int j = 0; j < 8; j += 4) {
            int n = bn + tx * 8 + j;
            float4 o;
            o.x = acc[i][j + 0] + bias[n + 0];
            o.y = acc[i][j + 1] + bias[n + 1];
            o.z = acc[i][j + 2] + bias[n + 2];
            o.w = acc[i][j + 3] + bias[n + 3];
            *(float4*)&C[(size_t)m * N + n] = o;
        }
    }
}

// ---------------------------------------------------------------------------
// RoPE in-place on Q and K; Q also gets the 1/sqrt(hd) score scale folded in.
// One thread per (b,t,h,i) pair, i in [0,32).
// ---------------------------------------------------------------------------
__global__ void rope_kernel(float* __restrict__ Q, float* __restrict__ K)
{
    int idx = blockIdx.x * blockDim.x + threadIdx.x;
    const int TOTAL = B_ * T_ * NHEAD * 32;
    if (idx >= TOTAL) return;
    int i = idx & 31;
    int h = (idx >> 5) & (NHEAD - 1);
    int t = (idx >> 9) & (T_ - 1);
    int b = idx >> 20;

    float freq = (float)t / powf(10000.0f, (float)i / 32.0f);
    float s, c;
    sincosf(freq, &s, &c);

    int base = ((b * T_ + t) * D_MODEL) + h * HEAD_DIM;
    const float scale = 0.125f;  // 64^-0.5

    float ql = Q[base + i], qr = Q[base + i + 32];
    Q[base + i]      = (ql * c - qr * s) * scale;
    Q[base + i + 32] = (ql * s + qr * c) * scale;

    float kl = K[base + i], kr = K[base + i + 32];
    K[base + i]      = kl * c - kr * s;
    K[base + i + 32] = kl * s + kr * c;
}

// ---------------------------------------------------------------------------
// Flash attention: 64-query tile per block, loop over 64-key tiles.
// grid = (T/64, NHEAD, B), 256 threads (16x16), 4x4 micro-tiles.
// smem: Qst[64][64] d-major, Kst[64][64] d-major, Vs[64][64] k-major,
//       Ps[64][65] q-major, fq[64], fk[64]
// ---------------------------------------------------------------------------
#define ATT_SMEM_FLOATS (64*64*3 + 64*65 + 128)
#define ATT_SMEM_BYTES (ATT_SMEM_FLOATS * 4)

__global__ __launch_bounds__(256) void attn_kernel(
    const float* __restrict__ Q, const float* __restrict__ K,
    const float* __restrict__ V, float* __restrict__ O,
    const float* __restrict__ frac,
    const float* __restrict__ alpha_pos, const float* __restrict__ alpha_neg)
{
    extern __shared__ float sm[];
    float* Qst = sm;                  // [64][64] (d, q)
    float* Kst = Qst + 64 * 64;       // [64][64] (d, k)
    float* Vs  = Kst + 64 * 64;       // [64][64] (k, dv)
    float* Ps  = Vs + 64 * 64;        // [64][65] (q, k) padded
    float* fq  = Ps + 64 * 65;
    float* fk  = fq + 64;

    int tid = threadIdx.x;
    int tx = tid % 16, ty = tid / 16;
    int qt = blockIdx.x;
    int h  = blockIdx.y;
    int b  = blockIdx.z;
    int t0 = qt * 64;

    const float ap = alpha_pos[h];
    const float an = alpha_neg[h];

    // Load Q tile (transpose to d-major)
    int lk = tid & 63;       // element row within tile
    int lc = tid >> 6;       // 0..3
#pragma unroll
    for (int it = 0; it < 4; it++) {
        int c = lc + it * 4;  // chunk 0..15 -> dims c*4 .. c*4+3
        const float* gp = &Q[((size_t)(b * T_ + t0 + lk)) * D_MODEL + h * HEAD_DIM + c * 4];
        float4 v = *(const float4*)gp;
        Qst[(c * 4 + 0) * 64 + lk] = v.x;
        Qst[(c * 4 + 1) * 64 + lk] = v.y;
        Qst[(c * 4 + 2) * 64 + lk] = v.z;
        Qst[(c * 4 + 3) * 64 + lk] = v.w;
    }
    if (tid < 64) fq[tid] = frac[b * T_ + t0 + tid];

    float m_i[4], l_i[4], o_acc[4][4];
#pragma unroll
    for (int i = 0; i < 4; i++) {
        m_i[i] = -INFINITY;
        l_i[i] = 0.f;
#pragma unroll
        for (int j = 0; j < 4; j++) o_acc[i][j] = 0.f;
    }
    __syncthreads();

    float fqr[4];
#pragma unroll
    for (int i = 0; i < 4; i++) fqr[i] = fq[ty * 4 + i];

    for (int kt = 0; kt < T_ / 64; kt++) {
        int tk0 = kt * 64;
        // Load K tile (transpose) + V tile (natural) + fk
#pragma unroll
        for (int it = 0; it < 4; it++) {
            int c = lc + it * 4;
            const float* gk = &K[((size_t)(b * T_ + tk0 + lk)) * D_MODEL + h * HEAD_DIM + c * 4];
            float4 kv = *(const float4*)gk;
            Kst[(c * 4 + 0) * 64 + lk] = kv.x;
            Kst[(c * 4 + 1) * 64 + lk] = kv.y;
            Kst[(c * 4 + 2) * 64 + lk] = kv.z;
            Kst[(c * 4 + 3) * 64 + lk] = kv.w;
            const float* gv = &V[((size_t)(b * T_ + tk0 + lk)) * D_MODEL + h * HEAD_DIM + c * 4];
            *(float4*)&Vs[lk * 64 + c * 4] = *(const float4*)gv;
        }
        if (tid < 64) fk[tid] = frac[b * T_ + tk0 + tid];
        __syncthreads();

        // S = Q K^T (Q pre-scaled)
        float s[4][4];
#pragma unroll
        for (int i = 0; i < 4; i++)
#pragma unroll
            for (int j = 0; j < 4; j++) s[i][j] = 0.f;

#pragma unroll 8
        for (int d = 0; d < 64; d++) {
            float4 a4 = *(const float4*)&Qst[d * 64 + ty * 4];
            float4 b4 = *(const float4*)&Kst[d * 64 + tx * 4];
            float a[4] = {a4.x, a4.y, a4.z, a4.w};
            float bb[4] = {b4.x, b4.y, b4.z, b4.w};
#pragma unroll
            for (int i = 0; i < 4; i++)
#pragma unroll
                for (int j = 0; j < 4; j++)
                    s[i][j] += a[i] * bb[j];
        }

        // frac bias
        float fkc[4];
#pragma unroll
        for (int j = 0; j < 4; j++) fkc[j] = fk[tx * 4 + j];
#pragma unroll
        for (int i = 0; i < 4; i++)
#pragma unroll
            for (int j = 0; j < 4; j++) {
                float d = fkc[j] - fqr[i];
                s[i][j] += (d > 0.f) ? ap * d : an * d;
            }

        // online softmax update (rows reduced across the 16 tx lanes)
#pragma unroll
        for (int i = 0; i < 4; i++) {
            float m = fmaxf(fmaxf(s[i][0], s[i][1]), fmaxf(s[i][2], s[i][3]));
            m = fmaxf(m, __shfl_xor_sync(0xffffffffu, m, 1));
            m = fmaxf(m, __shfl_xor_sync(0xffffffffu, m, 2));
            m = fmaxf(m, __shfl_xor_sync(0xffffffffu, m, 4));
            m = fmaxf(m, __shfl_xor_sync(0xffffffffu, m, 8));
            float m_new = fmaxf(m_i[i], m);
            float corr = expf(m_i[i] - m_new);
            float p0 = expf(s[i][0] - m_new);
            float p1 = expf(s[i][1] - m_new);
            float p2 = expf(s[i][2] - m_new);
            float p3 = expf(s[i][3] - m_new);
            float r = p0 + p1 + p2 + p3;
            r += __shfl_xor_sync(0xffffffffu, r, 1);
            r += __shfl_xor_sync(0xffffffffu, r, 2);
            r += __shfl_xor_sync(0xffffffffu, r, 4);
            r += __shfl_xor_sync(0xffffffffu, r, 8);
            l_i[i] = l_i[i] * corr + r;
            m_i[i] = m_new;
#pragma unroll
            for (int j = 0; j < 4; j++) o_acc[i][j] *= corr;
            // store P (q-major, padded rows)
            Ps[(ty * 4 + i) * 65 + tx * 4 + 0] = p0;
            Ps[(ty * 4 + i) * 65 + tx * 4 + 1] = p1;
            Ps[(ty * 4 + i) * 65 + tx * 4 + 2] = p2;
            Ps[(ty * 4 + i) * 65 + tx * 4 + 3] = p3;
        }
        __syncthreads();

        // O += P @ V
#pragma unroll 8
        for (int k = 0; k < 64; k++) {
            float a[4];
#pragma unroll
            for (int i = 0; i < 4; i++) a[i] = Ps[(ty * 4 + i) * 65 + k];
            float4 b4 = *(const float4*)&Vs[k * 64 + tx * 4];
            float bb[4] = {b4.x, b4.y, b4.z, b4.w};
#pragma unroll
            for (int i = 0; i < 4; i++)
#pragma unroll
                for (int j = 0; j < 4; j++)
                    o_acc[i][j] += a[i] * bb[j];
        }
        __syncthreads();
    }

    // epilogue: normalize and write to g_O in [B,T,D] layout
#pragma unroll
    for (int i = 0; i < 4; i++) {
        float inv = 1.0f / l_i[i];
        int t = t0 + ty * 4 + i;
        float4 o;
        o.x = o_acc[i][0] * inv;
        o.y = o_acc[i][1] * inv;
        o.z = o_acc[i][2] * inv;
        o.w = o_acc[i][3] * inv;
        *(float4*)&O[((size_t)(b * T_ + t)) * D_MODEL + h * HEAD_DIM + tx * 4] = o;
    }
}

// ---------------------------------------------------------------------------
// Launch
// Inputs: 0 query, 1 key, 2 value, 3 frac, 4 Wq, 5 Wk, 6 Wv, 7 Wo,
//         8 bq, 9 bk, 10 bv, 11 bo, 12 alpha_pos, 13 alpha_neg
// ---------------------------------------------------------------------------
extern "C" void kernel_launch(void* const* d_in, const int* in_sizes, int n_in,
                              void* d_out, int out_size)
{
    const float* query = (const float*)d_in[0];
    const float* key   = (const float*)d_in[1];
    const float* value = (const float*)d_in[2];
    const float* frac  = (const float*)d_in[3];
    const float* Wq    = (const float*)d_in[4];
    const float* Wk    = (const float*)d_in[5];
    const float* Wv    = (const float*)d_in[6];
    const float* Wo    = (const float*)d_in[7];
    const float* bq    = (const float*)d_in[8];
    const float* bk    = (const float*)d_in[9];
    const float* bv    = (const float*)d_in[10];
    const float* bo    = (const float*)d_in[11];
    const float* a_pos = (const float*)d_in[12];
    const float* a_neg = (const float*)d_in[13];
    float* out = (float*)d_out;

    float *pQ, *pK, *pV, *pO;
    cudaGetSymbolAddress((void**)&pQ, g_Q);
    cudaGetSymbolAddress((void**)&pK, g_K);
    cudaGetSymbolAddress((void**)&pV, g_V);
    cudaGetSymbolAddress((void**)&pO, g_O);

    dim3 gemm_grid(D_MODEL / 128, M_TOT / 128);

    sgemm_bias_kernel<<<gemm_grid, 256>>>(query, Wq, bq, pQ, M_TOT, D_MODEL, D_MODEL);
    sgemm_bias_kernel<<<gemm_grid, 256>>>(key,   Wk, bk, pK, M_TOT, D_MODEL, D_MODEL);
    sgemm_bias_kernel<<<gemm_grid, 256>>>(value, Wv, bv, pV, M_TOT, D_MODEL, D_MODEL);

    int rope_threads = B_ * T_ * NHEAD * 32;
    rope_kernel<<<(rope_threads + 255) / 256, 256>>>(pQ, pK);

    cudaFuncSetAttribute(attn_kernel, cudaFuncAttributeMaxDynamicSharedMemorySize, ATT_SMEM_BYTES);
    attn_kernel<<<dim3(T_ / 64, NHEAD, B_), 256, ATT_SMEM_BYTES>>>(
        pQ, pK, pV, pO, frac, a_pos, a_neg);

    sgemm_bias_kernel<<<gemm_grid, 256>>>(pO, Wo, bo, out, M_TOT, D_MODEL, D_MODEL);
}